// round 13
// baseline (speedup 1.0000x reference)
#include <cuda_runtime.h>
#include <cstdint>

// Problem constants
#define NB      8
#define NS      8192
#define DIM     1024
#define NE      16
#define NTOK    (NB * NS)          // 65536 tokens

#define M_TILE   32                // tokens per block = one warp's tile
#define THREADS  32
#define GRID     (NTOK / M_TILE)   // 2048 single-warp blocks -> ~13.8/SM, 1 wave

// Ambiguity margin for top-2 selection (logit scale). Split-TF32 noise ~1e-5;
// gaps below this are re-arbitrated in exact fp32.
#define GUARD_EPS 5e-3f

static __device__ __forceinline__ void split_tf32(float v, uint32_t& hi, uint32_t& lo) {
    uint32_t h;
    asm("cvt.rna.tf32.f32 %0, %1;" : "=r"(h) : "f"(v));
    hi = h;
    lo = __float_as_uint(v - __uint_as_float(h));
}

static __device__ __forceinline__ void mma_tf32(float d[4],
                                                uint32_t a0, uint32_t a1,
                                                uint32_t a2, uint32_t a3,
                                                uint32_t b0, uint32_t b1) {
    asm volatile(
        "mma.sync.aligned.m16n8k8.row.col.f32.tf32.tf32.f32 "
        "{%0,%1,%2,%3}, {%4,%5,%6,%7}, {%8,%9}, {%0,%1,%2,%3};"
        : "+f"(d[0]), "+f"(d[1]), "+f"(d[2]), "+f"(d[3])
        : "r"(a0), "r"(a1), "r"(a2), "r"(a3), "r"(b0), "r"(b1));
}

__global__ __launch_bounds__(THREADS, 16) void gating_mma_kernel(
    const float* __restrict__ x,
    const float* __restrict__ W,
    const float* __restrict__ bias,
    float* __restrict__ out)
{
    __shared__ float sLog[32][NE];     // 2KB, warp-private epilogue staging

    const int lane = threadIdx.x;
    const int g    = lane >> 2;        // fragment group 0..7
    const int tg   = lane & 3;         // thread-in-group 0..3
    const int tok0 = blockIdx.x * M_TILE;

    // K-PERMUTED fragments: for k8 group p, thread's K pair = {4tg+2p, 4tg+2p+1}.
    // Same per-thread permutation on A and B -> sum over K unchanged (exact).
    const float* xa = x + (size_t)(tok0 + g) * DIM + 4 * tg;  // rows g,+8,+16,+24
    const float* wb = W + (size_t)g * DIM + 4 * tg;           // experts g, g+8

    float acc[2][2][4];                // [m-tile][n-tile][frag]
    #pragma unroll
    for (int i = 0; i < 2; i++)
        #pragma unroll
        for (int j = 0; j < 2; j++)
            #pragma unroll
            for (int c = 0; c < 4; c++) acc[i][j][c] = 0.0f;

    #pragma unroll 2
    for (int k = 0; k < DIM; k += 16) {
        // 6 independent LDG.128 per thread (4 A rows, 2 B rows)
        float4 a[4], b[2];
        a[0] = *(const float4*)(xa + k);
        a[1] = *(const float4*)(xa + 8  * DIM + k);
        a[2] = *(const float4*)(xa + 16 * DIM + k);
        a[3] = *(const float4*)(xa + 24 * DIM + k);
        b[0] = *(const float4*)(wb + k);
        b[1] = *(const float4*)(wb + 8 * DIM + k);

        uint32_t ah[4][4], al[4][4], bh[2][4], bl[2][4];
        #pragma unroll
        for (int r = 0; r < 4; r++) {
            split_tf32(a[r].x, ah[r][0], al[r][0]);
            split_tf32(a[r].y, ah[r][1], al[r][1]);
            split_tf32(a[r].z, ah[r][2], al[r][2]);
            split_tf32(a[r].w, ah[r][3], al[r][3]);
        }
        #pragma unroll
        for (int r = 0; r < 2; r++) {
            split_tf32(b[r].x, bh[r][0], bl[r][0]);
            split_tf32(b[r].y, bh[r][1], bl[r][1]);
            split_tf32(b[r].z, bh[r][2], bl[r][2]);
            split_tf32(b[r].w, bh[r][3], bl[r][3]);
        }

        #pragma unroll
        for (int p = 0; p < 2; p++) {          // two k8 groups per k16
            const int c0 = 2 * p, c1 = 2 * p + 1;
            #pragma unroll
            for (int mt = 0; mt < 2; mt++) {
                const int r0 = mt * 2, r8 = mt * 2 + 1;
                #pragma unroll
                for (int nt = 0; nt < 2; nt++) {
                    float* d = acc[mt][nt];
                    // 3-term split TF32: hh + lh + hl (err ~1e-5; guarded below)
                    mma_tf32(d, ah[r0][c0], ah[r8][c0], ah[r0][c1], ah[r8][c1],
                                bh[nt][c0], bh[nt][c1]);
                    mma_tf32(d, al[r0][c0], al[r8][c0], al[r0][c1], al[r8][c1],
                                bh[nt][c0], bh[nt][c1]);
                    mma_tf32(d, ah[r0][c0], ah[r8][c0], ah[r0][c1], ah[r8][c1],
                                bl[nt][c0], bl[nt][c1]);
                }
            }
        }
    }

    // Scatter accumulators: D row g/g+8 (+16 mt) = token, col 2tg/2tg+1 (+8 nt).
    #pragma unroll
    for (int mt = 0; mt < 2; mt++)
        #pragma unroll
        for (int nt = 0; nt < 2; nt++) {
            sLog[mt * 16 + g    ][nt * 8 + 2 * tg    ] = acc[mt][nt][0];
            sLog[mt * 16 + g    ][nt * 8 + 2 * tg + 1] = acc[mt][nt][1];
            sLog[mt * 16 + g + 8][nt * 8 + 2 * tg    ] = acc[mt][nt][2];
            sLog[mt * 16 + g + 8][nt * 8 + 2 * tg + 1] = acc[mt][nt][3];
        }
    __syncwarp();

    // Epilogue: lane owns token tok0 + lane -> fully coalesced stores.
    const int token = tok0 + lane;
    const float* my = sLog[lane];

    float raw[NE];
    float mx = -1e30f;
    #pragma unroll
    for (int e = 0; e < NE; e++) {
        raw[e] = my[e] + __ldg(&bias[e]);
        mx = fmaxf(mx, raw[e]);
    }
    float lg[NE];
    float s = 0.0f;
    #pragma unroll
    for (int e = 0; e < NE; e++) { lg[e] = __expf(raw[e] - mx); s += lg[e]; }
    const float inv = 1.0f / s;

    // top-3 on logits; strict > keeps first index on ties (jax top_k).
    int i1 = 0; float m1 = raw[0];
    #pragma unroll
    for (int e = 1; e < NE; e++) if (raw[e] > m1) { m1 = raw[e]; i1 = e; }
    int i2 = -1; float m2 = -1e30f;
    #pragma unroll
    for (int e = 0; e < NE; e++) if (e != i1 && raw[e] > m2) { m2 = raw[e]; i2 = e; }
    int i3 = -1; float m3 = -1e30f;
    #pragma unroll
    for (int e = 0; e < NE; e++)
        if (e != i1 && e != i2 && raw[e] > m3) { m3 = raw[e]; i3 = e; }

    // Guard: if 2nd vs 3rd within split-TF32 noise, arbitrate in exact fp32.
    int sel2 = i2;
    if (m2 - m3 < GUARD_EPS) {
        const float4* xr = (const float4*)(x + (size_t)token * DIM);
        const float4* w2 = (const float4*)(W + (size_t)i2 * DIM);
        const float4* w3 = (const float4*)(W + (size_t)i3 * DIM);
        float s2 = 0.0f, s3 = 0.0f;
        for (int q = 0; q < DIM / 4; q++) {
            const float4 xv = xr[q], a2 = w2[q], a3 = w3[q];
            s2 = fmaf(xv.x, a2.x, s2); s2 = fmaf(xv.y, a2.y, s2);
            s2 = fmaf(xv.z, a2.z, s2); s2 = fmaf(xv.w, a2.w, s2);
            s3 = fmaf(xv.x, a3.x, s3); s3 = fmaf(xv.y, a3.y, s3);
            s3 = fmaf(xv.z, a3.z, s3); s3 = fmaf(xv.w, a3.w, s3);
        }
        s2 += __ldg(&bias[i2]); s3 += __ldg(&bias[i3]);
        // Exact ranking; tie (==) keeps lower index like jax top_k.
        if (s3 > s2 || (s3 == s2 && i3 < i2)) sel2 = i3;
    }

    float* gated = out;                         // [NE, NB, NS]
    float* wout  = out + (size_t)NE * NTOK;     // [NE, NB, NS]
    #pragma unroll
    for (int e = 0; e < NE; e++) {
        const float w = lg[e] * inv;
        wout [(size_t)e * NTOK + token] = w;
        gated[(size_t)e * NTOK + token] = (e == i1 || e == sel2) ? w : 0.0f;
    }
}

extern "C" void kernel_launch(void* const* d_in, const int* in_sizes, int n_in,
                              void* d_out, int out_size)
{
    (void)in_sizes; (void)n_in; (void)out_size;
    const float* x = (const float*)d_in[0];
    const float* W = (const float*)d_in[1];
    const float* b = (const float*)d_in[2];
    float* out = (float*)d_out;

    gating_mma_kernel<<<GRID, THREADS>>>(x, W, b, out);
}

// round 15
// speedup vs baseline: 1.4125x; 1.4125x over previous
#include <cuda_runtime.h>
#include <cstdint>

// Problem constants
#define NB      8
#define NS      8192
#define DIM     1024
#define NE      16
#define NTOK    (NB * NS)          // 65536 tokens

#define M_TILE   128               // tokens per block (32 per warp, 4 warps)
#define THREADS  128
#define GRID     (NTOK / M_TILE)   // 512

// cp.async pipeline: 32 stages of k=32, ring depth 3.
#define KST      32
#define NST      (DIM / KST)       // 32
#define DEPTH    3

// smem floats: sX[3][128][32] + sB[3][16][32]  (quad-swizzled)
#define SX_STAGE_F (M_TILE * KST)          // 4096
#define SB_STAGE_F (NE * KST)              // 512
#define SMEM_BYTES (DEPTH * (SX_STAGE_F + SB_STAGE_F) * 4)   // 55296

// Ambiguity margin for top-2 selection; split-TF32 noise ~1e-5.
#define GUARD_EPS 5e-3f

static __device__ __forceinline__ void split_tf32(float v, uint32_t& hi, uint32_t& lo) {
    uint32_t h;
    asm("cvt.rna.tf32.f32 %0, %1;" : "=r"(h) : "f"(v));
    hi = h;
    lo = __float_as_uint(v - __uint_as_float(h));
}
static __device__ __forceinline__ void mma_tf32(float d[4],
                                                uint32_t a0, uint32_t a1,
                                                uint32_t a2, uint32_t a3,
                                                uint32_t b0, uint32_t b1) {
    asm volatile(
        "mma.sync.aligned.m16n8k8.row.col.f32.tf32.tf32.f32 "
        "{%0,%1,%2,%3}, {%4,%5,%6,%7}, {%8,%9}, {%0,%1,%2,%3};"
        : "+f"(d[0]), "+f"(d[1]), "+f"(d[2]), "+f"(d[3])
        : "r"(a0), "r"(a1), "r"(a2), "r"(a3), "r"(b0), "r"(b1));
}
static __device__ __forceinline__ uint32_t s2u(const void* p) {
    uint32_t a;
    asm("{ .reg .u64 t; cvta.to.shared.u64 t, %1; cvt.u32.u64 %0, t; }"
        : "=r"(a) : "l"(p));
    return a;
}
static __device__ __forceinline__ void cpa16(uint32_t dst, const float* src) {
    asm volatile("cp.async.cg.shared.global [%0], [%1], 16;"
                 :: "r"(dst), "l"(src) : "memory");
}

__global__ __launch_bounds__(THREADS, 4) void gating_mma_kernel(
    const float* __restrict__ x,
    const float* __restrict__ W,
    const float* __restrict__ bias,
    float* __restrict__ out)
{
    extern __shared__ float sm[];
    // sX at 0, sB after; sLog aliases sm[0..2047] (inside stage-0 A buffer,
    // only touched after the last compute which uses stage buffer 2).
    const uint32_t smu  = s2u(sm);
    const uint32_t sBu  = smu + DEPTH * SX_STAGE_F * 4;
    float* sLog = sm;                 // [4][32][16]

    const int tid  = threadIdx.x;
    const int wid  = tid >> 5;
    const int lane = tid & 31;
    const int g    = lane >> 2;        // fragment group 0..7
    const int tg   = lane & 3;         // thread-in-group 0..3
    const int tok0 = blockIdx.x * M_TILE;

    // --- cp.async copy slots (constant; stage adds buffer base + k offset) ---
    // A: 1024 quads/stage, 8 per thread. quad q: row=q>>3, col=q&7 (of 8 quads
    //    per 32-float row). Swizzled col' = col ^ (row&7).
    uint32_t dA[8];
    const float* gA[8];
    #pragma unroll
    for (int i = 0; i < 8; i++) {
        const int q = tid + 128 * i;
        const int r = q >> 3, c = q & 7;
        dA[i] = (uint32_t)(r * KST + ((c ^ (r & 7)) * 4)) * 4u;
        gA[i] = x + (size_t)(tok0 + r) * DIM + c * 4;
    }
    // B: 128 quads/stage, 1 per thread.
    const int  rB = tid >> 3, cB = tid & 7;
    const uint32_t dB = (uint32_t)(rB * KST + ((cB ^ (rB & 7)) * 4)) * 4u;
    const float*   gB = W + (size_t)rB * DIM + cB * 4;

    // Prologue: stages 0..DEPTH-2
    #pragma unroll
    for (int s = 0; s < DEPTH - 1; s++) {
        const uint32_t xb = smu + (uint32_t)(s * SX_STAGE_F * 4);
        const uint32_t bb = sBu + (uint32_t)(s * SB_STAGE_F * 4);
        #pragma unroll
        for (int i = 0; i < 8; i++) cpa16(xb + dA[i], gA[i] + s * KST);
        cpa16(bb + dB, gB + s * KST);
        asm volatile("cp.async.commit_group;" ::: "memory");
    }

    float acc[2][2][4];                // [m-tile][n-tile][frag]
    #pragma unroll
    for (int i = 0; i < 2; i++)
        #pragma unroll
        for (int j = 0; j < 2; j++)
            #pragma unroll
            for (int c = 0; c < 4; c++) acc[i][j][c] = 0.0f;

    for (int j = 0; j < NST; j++) {
        // Stage j complete when <=1 newer group outstanding.
        asm volatile("cp.async.wait_group 1;" ::: "memory");
        __syncthreads();

        // Prefetch stage j+2 into ring slot (j+2)%3 (freed by sync above).
        const int pf = j + DEPTH - 1;
        if (pf < NST) {
            const uint32_t xb = smu + (uint32_t)((pf % DEPTH) * SX_STAGE_F * 4);
            const uint32_t bb = sBu + (uint32_t)((pf % DEPTH) * SB_STAGE_F * 4);
            #pragma unroll
            for (int i = 0; i < 8; i++) cpa16(xb + dA[i], gA[i] + pf * KST);
            cpa16(bb + dB, gB + pf * KST);
        }
        asm volatile("cp.async.commit_group;" ::: "memory");

        // Compute stage j from smem. Rows: wid*32 + g + 8m (row&7 == g).
        const float* bx = sm + (j % DEPTH) * SX_STAGE_F;
        const float* bb = sm + DEPTH * SX_STAGE_F + (j % DEPTH) * SB_STAGE_F;

        #pragma unroll
        for (int h = 0; h < 2; h++) {          // two k16 halves per stage
            const int qs = ((tg + 4 * h) ^ g) * 4;   // swizzled quad offset
            float4 a[4], b[2];
            #pragma unroll
            for (int m = 0; m < 4; m++)
                a[m] = *(const float4*)(bx + (wid * 32 + g + 8 * m) * KST + qs);
            b[0] = *(const float4*)(bb + g       * KST + qs);
            b[1] = *(const float4*)(bb + (g + 8) * KST + qs);

            uint32_t ah[4][4], al[4][4], bh[2][4], bl[2][4];
            #pragma unroll
            for (int r = 0; r < 4; r++) {
                split_tf32(a[r].x, ah[r][0], al[r][0]);
                split_tf32(a[r].y, ah[r][1], al[r][1]);
                split_tf32(a[r].z, ah[r][2], al[r][2]);
                split_tf32(a[r].w, ah[r][3], al[r][3]);
            }
            #pragma unroll
            for (int r = 0; r < 2; r++) {
                split_tf32(b[r].x, bh[r][0], bl[r][0]);
                split_tf32(b[r].y, bh[r][1], bl[r][1]);
                split_tf32(b[r].z, bh[r][2], bl[r][2]);
                split_tf32(b[r].w, bh[r][3], bl[r][3]);
            }

            #pragma unroll
            for (int p = 0; p < 2; p++) {      // two k8 groups per k16
                const int c0 = 2 * p, c1 = 2 * p + 1;
                #pragma unroll
                for (int mt = 0; mt < 2; mt++) {
                    const int r0 = mt * 2, r8 = mt * 2 + 1;
                    #pragma unroll
                    for (int nt = 0; nt < 2; nt++) {
                        float* d = acc[mt][nt];
                        // 3-term split TF32: hh + lh + hl (guarded selection)
                        mma_tf32(d, ah[r0][c0], ah[r8][c0], ah[r0][c1], ah[r8][c1],
                                    bh[nt][c0], bh[nt][c1]);
                        mma_tf32(d, al[r0][c0], al[r8][c0], al[r0][c1], al[r8][c1],
                                    bh[nt][c0], bh[nt][c1]);
                        mma_tf32(d, ah[r0][c0], ah[r8][c0], ah[r0][c1], ah[r8][c1],
                                    bl[nt][c0], bl[nt][c1]);
                    }
                }
            }
        }
    }

    // Scatter accumulators into warp-private sLog (aliases stage-0 A buffer;
    // final compute used stage buffer 2, so no overlap).
    #pragma unroll
    for (int mt = 0; mt < 2; mt++)
        #pragma unroll
        for (int nt = 0; nt < 2; nt++) {
            float* row0 = sLog + (wid * 32 + mt * 16 + g)     * NE;
            float* row8 = sLog + (wid * 32 + mt * 16 + g + 8) * NE;
            row0[nt * 8 + 2 * tg]     = acc[mt][nt][0];
            row0[nt * 8 + 2 * tg + 1] = acc[mt][nt][1];
            row8[nt * 8 + 2 * tg]     = acc[mt][nt][2];
            row8[nt * 8 + 2 * tg + 1] = acc[mt][nt][3];
        }
    __syncwarp();

    // Epilogue: thread t owns token tok0 + t (reads own warp's staging).
    const int token = tok0 + tid;
    const float* my = sLog + tid * NE;

    float raw[NE];
    float mx = -1e30f;
    #pragma unroll
    for (int e = 0; e < NE; e++) {
        raw[e] = my[e] + __ldg(&bias[e]);
        mx = fmaxf(mx, raw[e]);
    }
    float lg[NE];
    float s = 0.0f;
    #pragma unroll
    for (int e = 0; e < NE; e++) { lg[e] = __expf(raw[e] - mx); s += lg[e]; }
    const float inv = 1.0f / s;

    // top-3 on logits; strict > keeps first index on ties (jax top_k).
    int i1 = 0; float m1 = raw[0];
    #pragma unroll
    for (int e = 1; e < NE; e++) if (raw[e] > m1) { m1 = raw[e]; i1 = e; }
    int i2 = -1; float m2 = -1e30f;
    #pragma unroll
    for (int e = 0; e < NE; e++) if (e != i1 && raw[e] > m2) { m2 = raw[e]; i2 = e; }
    int i3 = -1; float m3 = -1e30f;
    #pragma unroll
    for (int e = 0; e < NE; e++)
        if (e != i1 && e != i2 && raw[e] > m3) { m3 = raw[e]; i3 = e; }

    // Guard: if 2nd vs 3rd within split-TF32 noise, arbitrate in exact fp32.
    int sel2 = i2;
    if (m2 - m3 < GUARD_EPS) {
        const float4* xr = (const float4*)(x + (size_t)token * DIM);
        const float4* w2 = (const float4*)(W + (size_t)i2 * DIM);
        const float4* w3 = (const float4*)(W + (size_t)i3 * DIM);
        float s2 = 0.0f, s3 = 0.0f;
        for (int q = 0; q < DIM / 4; q++) {
            const float4 xv = xr[q], a2 = w2[q], a3 = w3[q];
            s2 = fmaf(xv.x, a2.x, s2); s2 = fmaf(xv.y, a2.y, s2);
            s2 = fmaf(xv.z, a2.z, s2); s2 = fmaf(xv.w, a2.w, s2);
            s3 = fmaf(xv.x, a3.x, s3); s3 = fmaf(xv.y, a3.y, s3);
            s3 = fmaf(xv.z, a3.z, s3); s3 = fmaf(xv.w, a3.w, s3);
        }
        s2 += __ldg(&bias[i2]); s3 += __ldg(&bias[i3]);
        if (s3 > s2 || (s3 == s2 && i3 < i2)) sel2 = i3;
    }

    float* gated = out;                         // [NE, NB, NS]
    float* wout  = out + (size_t)NE * NTOK;     // [NE, NB, NS]
    #pragma unroll
    for (int e = 0; e < NE; e++) {
        const float w = lg[e] * inv;
        wout [(size_t)e * NTOK + token] = w;
        gated[(size_t)e * NTOK + token] = (e == i1 || e == sel2) ? w : 0.0f;
    }
}

extern "C" void kernel_launch(void* const* d_in, const int* in_sizes, int n_in,
                              void* d_out, int out_size)
{
    (void)in_sizes; (void)n_in; (void)out_size;
    const float* x = (const float*)d_in[0];
    const float* W = (const float*)d_in[1];
    const float* b = (const float*)d_in[2];
    float* out = (float*)d_out;

    cudaFuncSetAttribute(gating_mma_kernel,
                         cudaFuncAttributeMaxDynamicSharedMemorySize, SMEM_BYTES);
    gating_mma_kernel<<<GRID, THREADS, SMEM_BYTES>>>(x, W, b, out);
}

// round 16
// speedup vs baseline: 1.4168x; 1.0030x over previous
#include <cuda_runtime.h>
#include <cstdint>

// Problem constants
#define NB      8
#define NS      8192
#define DIM     1024
#define NE      16
#define NTOK    (NB * NS)          // 65536 tokens

#define M_TILE   128               // tokens per block (32 per warp, 4 warps)
#define THREADS  128
#define GRID     (NTOK / M_TILE)   // 512

// Per-warp cp.async ring: 32 stages of k=32, depth 3.
#define KST      32
#define NST      (DIM / KST)       // 32
#define DEPTH    3
#define WSTG_F   (32 * KST)        // floats per warp-stage (4KB)
#define SMEM_BYTES (4 * DEPTH * WSTG_F * 4)    // 48KB

// Ambiguity margin for top-2 selection; split noise ~2^-22 * |logit|.
#define GUARD_EPS 5e-3f

// Mask split: hi = v with low 13 mantissa bits cleared (exactly tf32-representable,
// LOP3), lo = v - hi (exact FSUB; MMA truncation of lo -> err ~2^-22 |v|).
static __device__ __forceinline__ void split_mask(float v, uint32_t& hi, uint32_t& lo) {
    const uint32_t h = __float_as_uint(v) & 0xFFFFE000u;
    hi = h;
    lo = __float_as_uint(v - __uint_as_float(h));
}
static __device__ __forceinline__ void mma_tf32(float d[4],
                                                uint32_t a0, uint32_t a1,
                                                uint32_t a2, uint32_t a3,
                                                uint32_t b0, uint32_t b1) {
    asm volatile(
        "mma.sync.aligned.m16n8k8.row.col.f32.tf32.tf32.f32 "
        "{%0,%1,%2,%3}, {%4,%5,%6,%7}, {%8,%9}, {%0,%1,%2,%3};"
        : "+f"(d[0]), "+f"(d[1]), "+f"(d[2]), "+f"(d[3])
        : "r"(a0), "r"(a1), "r"(a2), "r"(a3), "r"(b0), "r"(b1));
}
static __device__ __forceinline__ uint32_t s2u(const void* p) {
    uint32_t a;
    asm("{ .reg .u64 t; cvta.to.shared.u64 t, %1; cvt.u32.u64 %0, t; }"
        : "=r"(a) : "l"(p));
    return a;
}
static __device__ __forceinline__ void cpa16(uint32_t dst, const float* src) {
    asm volatile("cp.async.cg.shared.global [%0], [%1], 16;"
                 :: "r"(dst), "l"(src) : "memory");
}

__global__ __launch_bounds__(THREADS, 4) void gating_mma_kernel(
    const float* __restrict__ x,
    const float* __restrict__ W,
    const float* __restrict__ bias,
    float* __restrict__ out)
{
    extern __shared__ float sm[];

    const int tid  = threadIdx.x;
    const int wid  = tid >> 5;
    const int lane = tid & 31;
    const int g    = lane >> 2;        // fragment group 0..7
    const int tg   = lane & 3;         // thread-in-group 0..3
    const int tokw = blockIdx.x * M_TILE + wid * 32;   // warp's 32-token base

    // Warp-private ring: sm + wid * DEPTH * WSTG_F
    float* ring = sm + wid * DEPTH * WSTG_F;
    const uint32_t ringu = s2u(ring);

    // cp.async slots: 256 quads/warp-stage, 8 per lane.
    // quad q = lane + 32*i: row = q>>3 (0..31), col = q&7; swizzle col ^= row&7.
    uint32_t dA[8];
    const float* gA[8];
    #pragma unroll
    for (int i = 0; i < 8; i++) {
        const int q = lane + 32 * i;
        const int r = q >> 3, c = q & 7;
        dA[i] = (uint32_t)(r * KST + ((c ^ (r & 7)) * 4)) * 4u;
        gA[i] = x + (size_t)(tokw + r) * DIM + c * 4;
    }

    // Prologue: stages 0..DEPTH-2 (per-thread commit groups).
    #pragma unroll
    for (int s = 0; s < DEPTH - 1; s++) {
        const uint32_t xb = ringu + (uint32_t)(s * WSTG_F * 4);
        #pragma unroll
        for (int i = 0; i < 8; i++) cpa16(xb + dA[i], gA[i] + s * KST);
        asm volatile("cp.async.commit_group;" ::: "memory");
    }

    // B direct from global (L1-resident after warmup): experts g, g+8.
    const float* wb = W + (size_t)g * DIM;

    float acc[2][2][4];                // [m-tile][n-tile][frag]
    #pragma unroll
    for (int i = 0; i < 2; i++)
        #pragma unroll
        for (int j2 = 0; j2 < 2; j2++)
            #pragma unroll
            for (int c = 0; c < 4; c++) acc[i][j2][c] = 0.0f;

    for (int j = 0; j < NST; j++) {
        // Wait own stage j (<=1 newer group outstanding), warp-local sync.
        asm volatile("cp.async.wait_group 1;" ::: "memory");
        __syncwarp();

        // Prefetch stage j+2 into freed ring slot (per-warp, no block barrier).
        const int pf = j + DEPTH - 1;
        if (pf < NST) {
            const uint32_t xb = ringu + (uint32_t)((pf % DEPTH) * WSTG_F * 4);
            #pragma unroll
            for (int i = 0; i < 8; i++) cpa16(xb + dA[i], gA[i] + pf * KST);
        }
        asm volatile("cp.async.commit_group;" ::: "memory");

        const float* bx = ring + (j % DEPTH) * WSTG_F;

        #pragma unroll
        for (int h = 0; h < 2; h++) {          // two k16 halves per stage
            const int kq = tg + 4 * h;         // logical quad within 32-k slab
            const int qs = (kq ^ g) * 4;       // swizzled smem offset
            const int kg = j * KST + kq * 4;   // global k for B

            float4 a[4], b[2];
            #pragma unroll
            for (int m = 0; m < 4; m++)
                a[m] = *(const float4*)(bx + (g + 8 * m) * KST + qs);
            b[0] = *(const float4*)(wb + kg);             // expert g
            b[1] = *(const float4*)(wb + 8 * DIM + kg);   // expert g+8

            uint32_t ah[4][4], al[4][4], bh[2][4], bl[2][4];
            #pragma unroll
            for (int r = 0; r < 4; r++) {
                split_mask(a[r].x, ah[r][0], al[r][0]);
                split_mask(a[r].y, ah[r][1], al[r][1]);
                split_mask(a[r].z, ah[r][2], al[r][2]);
                split_mask(a[r].w, ah[r][3], al[r][3]);
            }
            #pragma unroll
            for (int r = 0; r < 2; r++) {
                split_mask(b[r].x, bh[r][0], bl[r][0]);
                split_mask(b[r].y, bh[r][1], bl[r][1]);
                split_mask(b[r].z, bh[r][2], bl[r][2]);
                split_mask(b[r].w, bh[r][3], bl[r][3]);
            }

            #pragma unroll
            for (int p = 0; p < 2; p++) {      // two k8 groups per k16
                const int c0 = 2 * p, c1 = 2 * p + 1;
                #pragma unroll
                for (int mt = 0; mt < 2; mt++) {
                    const int r0 = mt * 2, r8 = mt * 2 + 1;
                    #pragma unroll
                    for (int nt = 0; nt < 2; nt++) {
                        float* d = acc[mt][nt];
                        // 3-term split TF32: hh + lh + hl (guarded selection)
                        mma_tf32(d, ah[r0][c0], ah[r8][c0], ah[r0][c1], ah[r8][c1],
                                    bh[nt][c0], bh[nt][c1]);
                        mma_tf32(d, al[r0][c0], al[r8][c0], al[r0][c1], al[r8][c1],
                                    bh[nt][c0], bh[nt][c1]);
                        mma_tf32(d, ah[r0][c0], ah[r8][c0], ah[r0][c1], ah[r8][c1],
                                    bl[nt][c0], bl[nt][c1]);
                    }
                }
            }
        }
    }

    // Epilogue staging: reuse warp-private ring as sLog[32][16] (all stages
    // consumed; only this warp touches its ring -> __syncwarp suffices).
    asm volatile("cp.async.wait_group 0;" ::: "memory");
    __syncwarp();
    float* sLog = ring;
    #pragma unroll
    for (int mt = 0; mt < 2; mt++)
        #pragma unroll
        for (int nt = 0; nt < 2; nt++) {
            float* row0 = sLog + (mt * 16 + g)     * NE;
            float* row8 = sLog + (mt * 16 + g + 8) * NE;
            row0[nt * 8 + 2 * tg]     = acc[mt][nt][0];
            row0[nt * 8 + 2 * tg + 1] = acc[mt][nt][1];
            row8[nt * 8 + 2 * tg]     = acc[mt][nt][2];
            row8[nt * 8 + 2 * tg + 1] = acc[mt][nt][3];
        }
    __syncwarp();

    // Epilogue: lane owns token tokw + lane -> coalesced 128B segments.
    const int token = tokw + lane;
    const float* my = sLog + lane * NE;

    float raw[NE];
    float mx = -1e30f;
    #pragma unroll
    for (int e = 0; e < NE; e++) {
        raw[e] = my[e] + __ldg(&bias[e]);
        mx = fmaxf(mx, raw[e]);
    }
    float lg[NE];
    float s = 0.0f;
    #pragma unroll
    for (int e = 0; e < NE; e++) { lg[e] = __expf(raw[e] - mx); s += lg[e]; }
    const float inv = 1.0f / s;

    // top-3 on logits; strict > keeps first index on ties (jax top_k).
    int i1 = 0; float m1 = raw[0];
    #pragma unroll
    for (int e = 1; e < NE; e++) if (raw[e] > m1) { m1 = raw[e]; i1 = e; }
    int i2 = -1; float m2 = -1e30f;
    #pragma unroll
    for (int e = 0; e < NE; e++) if (e != i1 && raw[e] > m2) { m2 = raw[e]; i2 = e; }
    int i3 = -1; float m3 = -1e30f;
    #pragma unroll
    for (int e = 0; e < NE; e++)
        if (e != i1 && e != i2 && raw[e] > m3) { m3 = raw[e]; i3 = e; }

    // Guard: if 2nd vs 3rd within split noise, arbitrate in exact fp32.
    int sel2 = i2;
    if (m2 - m3 < GUARD_EPS) {
        const float4* xr = (const float4*)(x + (size_t)token * DIM);
        const float4* w2 = (const float4*)(W + (size_t)i2 * DIM);
        const float4* w3 = (const float4*)(W + (size_t)i3 * DIM);
        float s2 = 0.0f, s3 = 0.0f;
        for (int q = 0; q < DIM / 4; q++) {
            const float4 xv = xr[q], a2 = w2[q], a3 = w3[q];
            s2 = fmaf(xv.x, a2.x, s2); s2 = fmaf(xv.y, a2.y, s2);
            s2 = fmaf(xv.z, a2.z, s2); s2 = fmaf(xv.w, a2.w, s2);
            s3 = fmaf(xv.x, a3.x, s3); s3 = fmaf(xv.y, a3.y, s3);
            s3 = fmaf(xv.z, a3.z, s3); s3 = fmaf(xv.w, a3.w, s3);
        }
        s2 += __ldg(&bias[i2]); s3 += __ldg(&bias[i3]);
        if (s3 > s2 || (s3 == s2 && i3 < i2)) sel2 = i3;
    }

    float* gated = out;                         // [NE, NB, NS]
    float* wout  = out + (size_t)NE * NTOK;     // [NE, NB, NS]
    #pragma unroll
    for (int e = 0; e < NE; e++) {
        const float w = lg[e] * inv;
        wout [(size_t)e * NTOK + token] = w;
        gated[(size_t)e * NTOK + token] = (e == i1 || e == sel2) ? w : 0.0f;
    }
}

extern "C" void kernel_launch(void* const* d_in, const int* in_sizes, int n_in,
                              void* d_out, int out_size)
{
    (void)in_sizes; (void)n_in; (void)out_size;
    const float* x = (const float*)d_in[0];
    const float* W = (const float*)d_in[1];
    const float* b = (const float*)d_in[2];
    float* out = (float*)d_out;

    cudaFuncSetAttribute(gating_mma_kernel,
                         cudaFuncAttributeMaxDynamicSharedMemorySize, SMEM_BYTES);
    gating_mma_kernel<<<GRID, THREADS, SMEM_BYTES>>>(x, W, b, out);
}